// round 14
// baseline (speedup 1.0000x reference)
#include <cuda_runtime.h>
#include <cuda_bf16.h>

#define NN 8192
#define T  64
#define NT (NN / T)                 // 128
#define NPAIR (NT * (NT + 1) / 2)   // 8256 tile pairs

// Deterministic partial row sums: g_part[k][i] = degree contribution to row i
// from tile-column k. Written exactly once per slot. 4 MB scratch.
__device__ float g_part[NT * NN];
__device__ float g_dis[NN];

// Decode linear pair index -> (bi, bj), bi <= bj, row-major over upper triangle.
__device__ __forceinline__ void pair_decode(int idx, int& bi, int& bj) {
    const int M2 = 2 * NT + 1;
    int i = (int)(((float)M2 - sqrtf((float)M2 * (float)M2 - 8.0f * (float)idx)) * 0.5f);
    while ((i * (2 * NT - i + 1)) / 2 > idx) --i;
    while (((i + 1) * (2 * NT - i)) / 2 <= idx) ++i;
    bi = i;
    bj = idx - (i * (2 * NT - i + 1)) / 2 + i;
}

// ---------------------------------------------------------------------------
// Pass 1 (degrees): R11 configuration (best measured): scalar conflict-free
// map (c = t&63), 16-deep A register prefetch before the barrier, B staged
// via LDG->STS, 32 regs, full occupancy. Default cache policy on purpose:
// the tail tiles stay L2-resident for pass2's reverse-order handoff.
// ---------------------------------------------------------------------------
__global__ __launch_bounds__(256) void pass1_degrees(const float* __restrict__ adj) {
    int bi, bj;
    pair_decode(blockIdx.x, bi, bj);

    __shared__ float Bs[T][T + 1];
    __shared__ float rpartS[4][T];
    __shared__ float cpartS[4][T];

    const int t  = threadIdx.x;
    const int c  = t & 63;
    const int rg = t >> 6;
    const size_t I0 = (size_t)bi * T, J0 = (size_t)bj * T;

    // Prefetch the 16 A values this thread will consume (coalesced LDG.32).
    float a[16];
    #pragma unroll
    for (int k = 0; k < 16; ++k)
        a[k] = adj[(I0 + rg * 16 + k) * NN + J0 + c];

    // Stage B (coalesced LDG; STS bank (rr + c)%32 -> conflict-free).
    #pragma unroll
    for (int k = 0; k < 16; ++k) {
        int rr = rg * 16 + k;
        Bs[rr][c] = adj[(J0 + rr) * NN + I0 + c];
    }
    __syncthreads();

    const bool diag = (bi == bj);
    float colAcc = 0.0f;

    // m = max(A, B^T); column sums in a register; store m back in place.
    #pragma unroll
    for (int k = 0; k < 16; ++k) {
        int r = rg * 16 + k;
        float m = fmaxf(a[k], Bs[c][r]);         // bank (c+r)%32 -> conflict-free
        if (diag && r == c) m = 1.0f;
        colAcc += m;
        Bs[c][r] = m;                            // same slot just read -> no hazard
    }
    cpartS[rg][c] = colAcc;
    __syncthreads();

    // Bs[c][r] holds m(r,c): row sums of M are conflict-free smem reads.
    float rowAcc = 0.0f;
    #pragma unroll
    for (int k = 0; k < 16; ++k)
        rowAcc += Bs[rg * 16 + k][c];
    rpartS[rg][c] = rowAcc;
    __syncthreads();

    if (t < T) {
        g_part[bj * NN + I0 + t] =
            (rpartS[0][t] + rpartS[1][t]) + (rpartS[2][t] + rpartS[3][t]);
        if (!diag)
            g_part[bi * NN + J0 + t] =
                (cpartS[0][t] + cpartS[1][t]) + (cpartS[2][t] + cpartS[3][t]);
    }
}

// ---------------------------------------------------------------------------
// Degree reduce + rsqrt: 256 blocks x 128 threads (spans all SMs); 4 k-slices
// per row combined via smem. Fully coalesced, deterministic fixed-order sums.
// ---------------------------------------------------------------------------
__global__ __launch_bounds__(128) void reduce_rsqrt_kernel() {
    __shared__ float part[4][32];
    const int t = threadIdx.x;
    const int i = blockIdx.x * 32 + (t & 31);
    const int q = t >> 5;

    float s = 0.f;
    #pragma unroll
    for (int kk = 0; kk < NT / 4; ++kk)
        s += g_part[(q + 4 * kk) * NN + i];
    part[q][t & 31] = s;
    __syncthreads();

    if (t < 32) {
        float tot = (part[0][t] + part[1][t]) + (part[2][t] + part[3][t]);
        g_dis[blockIdx.x * 32 + t] = rsqrtf(tot);
    }
}

// ---------------------------------------------------------------------------
// Pass 2 (write), float4 + streaming cache policy: adj read exactly once
// (__ldcs), out written once with zero reuse (__stcs) — keeps L2 free for
// read-ahead and the pass1 handoff. out is symmetric: compute scaled s once,
// STG.128 out[I,J], stage transposed in place, STG.128 the mirror block.
// Reverse triangle order for L2 reuse of pass1's tail tiles.
// ---------------------------------------------------------------------------
__global__ __launch_bounds__(256) void pass2_write(const float* __restrict__ adj,
                                                   float* __restrict__ out) {
    int bi, bj;
    pair_decode(NPAIR - 1 - (int)blockIdx.x, bi, bj);

    __shared__ float Bs[T][T + 1];
    __shared__ float dI[T], dJ[T];

    const int t  = threadIdx.x;
    const int c4 = (t & 15) * 4;
    const int rg = t >> 4;
    const size_t I0 = (size_t)bi * T, J0 = (size_t)bj * T;

    #pragma unroll
    for (int k = 0; k < 4; ++k) {
        int rr = rg + 16 * k;
        float4 b = __ldcs(reinterpret_cast<const float4*>(&adj[(J0 + rr) * NN + I0 + c4]));
        Bs[rr][c4 + 0] = b.x; Bs[rr][c4 + 1] = b.y;
        Bs[rr][c4 + 2] = b.z; Bs[rr][c4 + 3] = b.w;
    }
    if (t < T)          dI[t]     = g_dis[I0 + t];
    else if (t < 2 * T) dJ[t - T] = g_dis[J0 + (t - T)];
    __syncthreads();

    const bool diag = (bi == bj);
    const float dj0 = dJ[c4 + 0], dj1 = dJ[c4 + 1];
    const float dj2 = dJ[c4 + 2], dj3 = dJ[c4 + 3];

    #pragma unroll
    for (int k = 0; k < 4; ++k) {
        int r = rg + 16 * k;
        float4 a = __ldcs(reinterpret_cast<const float4*>(&adj[(I0 + r) * NN + J0 + c4]));
        const float dir = dI[r];
        float m0 = fmaxf(a.x, Bs[c4 + 0][r]);
        float m1 = fmaxf(a.y, Bs[c4 + 1][r]);
        float m2 = fmaxf(a.z, Bs[c4 + 2][r]);
        float m3 = fmaxf(a.w, Bs[c4 + 3][r]);
        if (diag) {
            if (r == c4 + 0) m0 = 1.0f;
            if (r == c4 + 1) m1 = 1.0f;
            if (r == c4 + 2) m2 = 1.0f;
            if (r == c4 + 3) m3 = 1.0f;
        }
        float4 o;
        o.x = m0 * dir * dj0; o.y = m1 * dir * dj1;
        o.z = m2 * dir * dj2; o.w = m3 * dir * dj3;
        __stcs(reinterpret_cast<float4*>(&out[(I0 + r) * NN + J0 + c4]), o);
        Bs[c4 + 0][r] = o.x; Bs[c4 + 1][r] = o.y;
        Bs[c4 + 2][r] = o.z; Bs[c4 + 3][r] = o.w;
    }

    if (!diag) {
        __syncthreads();
        #pragma unroll
        for (int k = 0; k < 4; ++k) {
            int rr = rg + 16 * k;
            float4 o;
            o.x = Bs[rr][c4 + 0]; o.y = Bs[rr][c4 + 1];
            o.z = Bs[rr][c4 + 2]; o.w = Bs[rr][c4 + 3];
            __stcs(reinterpret_cast<float4*>(&out[(J0 + rr) * NN + I0 + c4]), o);
        }
    }
}

extern "C" void kernel_launch(void* const* d_in, const int* in_sizes, int n_in,
                              void* d_out, int out_size) {
    const float* adj = (const float*)d_in[0];
    float*       out = (float*)d_out;

    pass1_degrees<<<NPAIR, 256>>>(adj);
    reduce_rsqrt_kernel<<<NN / 32, 128>>>();
    pass2_write<<<NPAIR, 256>>>(adj, out);
}

// round 15
// speedup vs baseline: 1.0383x; 1.0383x over previous
#include <cuda_runtime.h>
#include <cuda_bf16.h>

#define NN 8192
#define T  64
#define NT (NN / T)                 // 128
#define NPAIR (NT * (NT + 1) / 2)   // 8256 tile pairs

// Deterministic partial row sums: g_part[k][i] = degree contribution to row i
// from tile-column k. Written exactly once per slot. 4 MB scratch.
__device__ float g_part[NT * NN];
__device__ float g_dis[NN];

// Decode linear pair index -> (bi, bj), bi <= bj, row-major over upper triangle.
__device__ __forceinline__ void pair_decode(int idx, int& bi, int& bj) {
    const int M2 = 2 * NT + 1;
    int i = (int)(((float)M2 - sqrtf((float)M2 * (float)M2 - 8.0f * (float)idx)) * 0.5f);
    while ((i * (2 * NT - i + 1)) / 2 > idx) --i;
    while (((i + 1) * (2 * NT - i)) / 2 <= idx) ++i;
    bi = i;
    bj = idx - (i * (2 * NT - i + 1)) / 2 + i;
}

// ---------------------------------------------------------------------------
// Pass 1 (degrees): R11 config (best measured: 48.4us). Scalar conflict-free
// map (c = t&63), 16-deep A register prefetch before the barrier, B staged
// LDG->STS. NEW: __ldcg on both streams — data is read-once into regs/smem,
// so skipping L1 allocation removes pure overhead while leaving L2 (and the
// pass1->pass2 handoff) untouched.
// ---------------------------------------------------------------------------
__global__ __launch_bounds__(256) void pass1_degrees(const float* __restrict__ adj) {
    int bi, bj;
    pair_decode(blockIdx.x, bi, bj);

    __shared__ float Bs[T][T + 1];
    __shared__ float rpartS[4][T];
    __shared__ float cpartS[4][T];

    const int t  = threadIdx.x;
    const int c  = t & 63;
    const int rg = t >> 6;
    const size_t I0 = (size_t)bi * T, J0 = (size_t)bj * T;

    // Prefetch the 16 A values this thread will consume (coalesced, L1-bypass).
    float a[16];
    #pragma unroll
    for (int k = 0; k < 16; ++k)
        a[k] = __ldcg(&adj[(I0 + rg * 16 + k) * NN + J0 + c]);

    // Stage B (coalesced LDG.cg; STS bank (rr + c)%32 -> conflict-free).
    #pragma unroll
    for (int k = 0; k < 16; ++k) {
        int rr = rg * 16 + k;
        Bs[rr][c] = __ldcg(&adj[(J0 + rr) * NN + I0 + c]);
    }
    __syncthreads();

    const bool diag = (bi == bj);
    float colAcc = 0.0f;

    // m = max(A, B^T); column sums in a register; store m back in place.
    #pragma unroll
    for (int k = 0; k < 16; ++k) {
        int r = rg * 16 + k;
        float m = fmaxf(a[k], Bs[c][r]);         // bank (c+r)%32 -> conflict-free
        if (diag && r == c) m = 1.0f;
        colAcc += m;
        Bs[c][r] = m;                            // same slot just read -> no hazard
    }
    cpartS[rg][c] = colAcc;
    __syncthreads();

    // Bs[c][r] holds m(r,c): row sums of M are conflict-free smem reads.
    float rowAcc = 0.0f;
    #pragma unroll
    for (int k = 0; k < 16; ++k)
        rowAcc += Bs[rg * 16 + k][c];
    rpartS[rg][c] = rowAcc;
    __syncthreads();

    if (t < T) {
        g_part[bj * NN + I0 + t] =
            (rpartS[0][t] + rpartS[1][t]) + (rpartS[2][t] + rpartS[3][t]);
        if (!diag)
            g_part[bi * NN + J0 + t] =
                (cpartS[0][t] + cpartS[1][t]) + (cpartS[2][t] + cpartS[3][t]);
    }
}

// ---------------------------------------------------------------------------
// Degree reduce + rsqrt: 128 blocks; 4 k-slices per row combined via smem.
// Fully coalesced, deterministic fixed-order sums.
// ---------------------------------------------------------------------------
__global__ __launch_bounds__(256) void reduce_rsqrt_kernel() {
    __shared__ float part[4][T];
    const int t = threadIdx.x;
    const int i = blockIdx.x * T + (t & 63);
    const int q = t >> 6;

    float s = 0.f;
    #pragma unroll
    for (int kk = 0; kk < NT / 4; ++kk)
        s += g_part[(q + 4 * kk) * NN + i];
    part[q][t & 63] = s;
    __syncthreads();

    if (t < T) {
        float tot = (part[0][t] + part[1][t]) + (part[2][t] + part[3][t]);
        g_dis[blockIdx.x * T + t] = rsqrtf(tot);
    }
}

// ---------------------------------------------------------------------------
// Pass 2 (write), float4, DEFAULT cache policy (measured best: streaming
// hints regressed by ~6us in R14). out is symmetric: compute scaled s once,
// STG.128 out[I,J], stage transposed in place, STG.128 the mirror block.
// Reverse triangle order for L2 reuse of pass1's tail tiles.
// ---------------------------------------------------------------------------
__global__ __launch_bounds__(256) void pass2_write(const float* __restrict__ adj,
                                                   float* __restrict__ out) {
    int bi, bj;
    pair_decode(NPAIR - 1 - (int)blockIdx.x, bi, bj);

    __shared__ float Bs[T][T + 1];
    __shared__ float dI[T], dJ[T];

    const int t  = threadIdx.x;
    const int c4 = (t & 15) * 4;
    const int rg = t >> 4;
    const size_t I0 = (size_t)bi * T, J0 = (size_t)bj * T;

    #pragma unroll
    for (int k = 0; k < 4; ++k) {
        int rr = rg + 16 * k;
        float4 b = *reinterpret_cast<const float4*>(&adj[(J0 + rr) * NN + I0 + c4]);
        Bs[rr][c4 + 0] = b.x; Bs[rr][c4 + 1] = b.y;
        Bs[rr][c4 + 2] = b.z; Bs[rr][c4 + 3] = b.w;
    }
    if (t < T)          dI[t]     = g_dis[I0 + t];
    else if (t < 2 * T) dJ[t - T] = g_dis[J0 + (t - T)];
    __syncthreads();

    const bool diag = (bi == bj);
    const float dj0 = dJ[c4 + 0], dj1 = dJ[c4 + 1];
    const float dj2 = dJ[c4 + 2], dj3 = dJ[c4 + 3];

    #pragma unroll
    for (int k = 0; k < 4; ++k) {
        int r = rg + 16 * k;
        float4 a = *reinterpret_cast<const float4*>(&adj[(I0 + r) * NN + J0 + c4]);
        const float dir = dI[r];
        float m0 = fmaxf(a.x, Bs[c4 + 0][r]);
        float m1 = fmaxf(a.y, Bs[c4 + 1][r]);
        float m2 = fmaxf(a.z, Bs[c4 + 2][r]);
        float m3 = fmaxf(a.w, Bs[c4 + 3][r]);
        if (diag) {
            if (r == c4 + 0) m0 = 1.0f;
            if (r == c4 + 1) m1 = 1.0f;
            if (r == c4 + 2) m2 = 1.0f;
            if (r == c4 + 3) m3 = 1.0f;
        }
        float4 o;
        o.x = m0 * dir * dj0; o.y = m1 * dir * dj1;
        o.z = m2 * dir * dj2; o.w = m3 * dir * dj3;
        *reinterpret_cast<float4*>(&out[(I0 + r) * NN + J0 + c4]) = o;
        Bs[c4 + 0][r] = o.x; Bs[c4 + 1][r] = o.y;
        Bs[c4 + 2][r] = o.z; Bs[c4 + 3][r] = o.w;
    }

    if (!diag) {
        __syncthreads();
        #pragma unroll
        for (int k = 0; k < 4; ++k) {
            int rr = rg + 16 * k;
            float4 o;
            o.x = Bs[rr][c4 + 0]; o.y = Bs[rr][c4 + 1];
            o.z = Bs[rr][c4 + 2]; o.w = Bs[rr][c4 + 3];
            *reinterpret_cast<float4*>(&out[(J0 + rr) * NN + I0 + c4]) = o;
        }
    }
}

extern "C" void kernel_launch(void* const* d_in, const int* in_sizes, int n_in,
                              void* d_out, int out_size) {
    const float* adj = (const float*)d_in[0];
    float*       out = (float*)d_out;

    pass1_degrees<<<NPAIR, 256>>>(adj);
    reduce_rsqrt_kernel<<<NN / T, 256>>>();
    pass2_write<<<NPAIR, 256>>>(adj, out);
}

// round 16
// speedup vs baseline: 1.0490x; 1.0103x over previous
#include <cuda_runtime.h>
#include <cuda_bf16.h>

#define NN 8192
#define T  64
#define NT (NN / T)                 // 128
#define NPAIR (NT * (NT + 1) / 2)   // 8256 tile pairs

// Deterministic partial row sums: g_part[k][i] = degree contribution to row i
// from tile-column k. Written exactly once per slot. 4 MB scratch.
__device__ float g_part[NT * NN];
__device__ float g_dis[NN];

// Decode linear pair index -> (bi, bj), bi <= bj, row-major over upper triangle.
__device__ __forceinline__ void pair_decode(int idx, int& bi, int& bj) {
    const int M2 = 2 * NT + 1;
    int i = (int)(((float)M2 - sqrtf((float)M2 * (float)M2 - 8.0f * (float)idx)) * 0.5f);
    while ((i * (2 * NT - i + 1)) / 2 > idx) --i;
    while (((i + 1) * (2 * NT - i)) / 2 <= idx) ++i;
    bi = i;
    bj = idx - (i * (2 * NT - i + 1)) / 2 + i;
}

// ---------------------------------------------------------------------------
// Pass 1 (degrees + materialize M^T): R11 structure (16-deep A prefetch,
// conflict-free scalar map, in-place smem transpose). NEW: the row-sum loop
// already reads Bs[rr][c] = M^T[rr][c]; write it straight to out[J0+rr][I0+c]
// (coalesced) so pass2 never has to re-read adj. The intermediate lands in
// L2 and is consumed/overwritten by pass2 before most of it spills to DRAM.
// ---------------------------------------------------------------------------
__global__ __launch_bounds__(256) void pass1_degrees(const float* __restrict__ adj,
                                                     float* __restrict__ out) {
    int bi, bj;
    pair_decode(blockIdx.x, bi, bj);

    __shared__ float Bs[T][T + 1];
    __shared__ float rpartS[4][T];
    __shared__ float cpartS[4][T];

    const int t  = threadIdx.x;
    const int c  = t & 63;
    const int rg = t >> 6;
    const size_t I0 = (size_t)bi * T, J0 = (size_t)bj * T;

    // Prefetch the 16 A values this thread will consume (coalesced LDG.32).
    float a[16];
    #pragma unroll
    for (int k = 0; k < 16; ++k)
        a[k] = adj[(I0 + rg * 16 + k) * NN + J0 + c];

    // Stage B (coalesced LDG; STS bank (rr + c)%32 -> conflict-free).
    #pragma unroll
    for (int k = 0; k < 16; ++k) {
        int rr = rg * 16 + k;
        Bs[rr][c] = adj[(J0 + rr) * NN + I0 + c];
    }
    __syncthreads();

    const bool diag = (bi == bj);
    float colAcc = 0.0f;

    // m = max(A, B^T); column sums in a register; store m back in place.
    #pragma unroll
    for (int k = 0; k < 16; ++k) {
        int r = rg * 16 + k;
        float m = fmaxf(a[k], Bs[c][r]);         // bank (c+r)%32 -> conflict-free
        if (diag && r == c) m = 1.0f;
        colAcc += m;
        Bs[c][r] = m;                            // same slot just read -> no hazard
    }
    cpartS[rg][c] = colAcc;
    __syncthreads();

    // Bs[c][r] holds M[r][c], i.e. Bs[rr][c] = M^T[rr][c]. Row sums of M are
    // conflict-free smem column reads; the SAME value streams out to the
    // lower-triangle scratch block out[J,I] (coalesced STG).
    float rowAcc = 0.0f;
    #pragma unroll
    for (int k = 0; k < 16; ++k) {
        int rr = rg * 16 + k;
        float v = Bs[rr][c];
        rowAcc += v;                              // NOTE: sums M^T rows? no:
        out[(J0 + rr) * NN + I0 + c] = v;         // M^T tile -> out[J,I]
    }
    // rowAcc above accumulated Bs[rr][c] over rr = column sum of M^T = row sum of M? 
    // Bs[rr][c] = M[c][rr]  -> sum over rr = row c sum of M. Store per-column partial:
    rpartS[rg][c] = rowAcc;
    __syncthreads();

    if (t < T) {
        // rpartS[*][t] holds partial sums over rr-chunks of row t of M.
        g_part[bj * NN + I0 + t] =
            (rpartS[0][t] + rpartS[1][t]) + (rpartS[2][t] + rpartS[3][t]);
        if (!diag)
            g_part[bi * NN + J0 + t] =
                (cpartS[0][t] + cpartS[1][t]) + (cpartS[2][t] + cpartS[3][t]);
    }
}

// ---------------------------------------------------------------------------
// Degree reduce + rsqrt: 128 blocks; 4 k-slices per row combined via smem.
// Fully coalesced, deterministic fixed-order sums.
// ---------------------------------------------------------------------------
__global__ __launch_bounds__(256) void reduce_rsqrt_kernel() {
    __shared__ float part[4][T];
    const int t = threadIdx.x;
    const int i = blockIdx.x * T + (t & 63);
    const int q = t >> 6;

    float s = 0.f;
    #pragma unroll
    for (int kk = 0; kk < NT / 4; ++kk)
        s += g_part[(q + 4 * kk) * NN + i];
    part[q][t & 63] = s;
    __syncthreads();

    if (t < T) {
        float tot = (part[0][t] + part[1][t]) + (part[2][t] + part[3][t]);
        g_dis[blockIdx.x * T + t] = rsqrtf(tot);
    }
}

// ---------------------------------------------------------------------------
// Pass 2 (scale + mirror): loads the M^T tile from out[J,I] (mostly L2-hit
// thanks to the reverse walk), scales, STG.128 the final upper block out[I,J],
// stages transposed in place, then overwrites out[J,I] with the final mirror
// block — killing the dirty intermediate before it ever reaches DRAM.
// No adj access at all.
// ---------------------------------------------------------------------------
__global__ __launch_bounds__(256) void pass2_write(float* __restrict__ out) {
    int bi, bj;
    pair_decode(NPAIR - 1 - (int)blockIdx.x, bi, bj);

    __shared__ float Bs[T][T + 1];
    __shared__ float dI[T], dJ[T];

    const int t  = threadIdx.x;
    const int c4 = (t & 15) * 4;
    const int rg = t >> 4;
    const size_t I0 = (size_t)bi * T, J0 = (size_t)bj * T;

    // Load M^T tile from the lower-triangle scratch (coalesced float4).
    #pragma unroll
    for (int k = 0; k < 4; ++k) {
        int rr = rg + 16 * k;
        float4 b = *reinterpret_cast<const float4*>(&out[(J0 + rr) * NN + I0 + c4]);
        Bs[rr][c4 + 0] = b.x; Bs[rr][c4 + 1] = b.y;
        Bs[rr][c4 + 2] = b.z; Bs[rr][c4 + 3] = b.w;
    }
    if (t < T)          dI[t]     = g_dis[I0 + t];
    else if (t < 2 * T) dJ[t - T] = g_dis[J0 + (t - T)];
    __syncthreads();

    const bool diag = (bi == bj);
    const float dj0 = dJ[c4 + 0], dj1 = dJ[c4 + 1];
    const float dj2 = dJ[c4 + 2], dj3 = dJ[c4 + 3];

    // Bs[c][r] = M[r][c]. Scale and write the upper block; stage transposed.
    #pragma unroll
    for (int k = 0; k < 4; ++k) {
        int r = rg + 16 * k;
        const float dir = dI[r];
        float4 o;
        o.x = Bs[c4 + 0][r] * dir * dj0;
        o.y = Bs[c4 + 1][r] * dir * dj1;
        o.z = Bs[c4 + 2][r] * dir * dj2;
        o.w = Bs[c4 + 3][r] * dir * dj3;
        *reinterpret_cast<float4*>(&out[(I0 + r) * NN + J0 + c4]) = o;
        Bs[c4 + 0][r] = o.x; Bs[c4 + 1][r] = o.y;     // same slots just read
        Bs[c4 + 2][r] = o.z; Bs[c4 + 3][r] = o.w;
    }

    if (!diag) {
        __syncthreads();
        #pragma unroll
        for (int k = 0; k < 4; ++k) {
            int rr = rg + 16 * k;
            float4 o;
            o.x = Bs[rr][c4 + 0]; o.y = Bs[rr][c4 + 1];
            o.z = Bs[rr][c4 + 2]; o.w = Bs[rr][c4 + 3];
            *reinterpret_cast<float4*>(&out[(J0 + rr) * NN + I0 + c4]) = o;
        }
    }
}

extern "C" void kernel_launch(void* const* d_in, const int* in_sizes, int n_in,
                              void* d_out, int out_size) {
    const float* adj = (const float*)d_in[0];
    float*       out = (float*)d_out;

    pass1_degrees<<<NPAIR, 256>>>(adj, out);
    reduce_rsqrt_kernel<<<NN / T, 256>>>();
    pass2_write<<<NPAIR, 256>>>(out);
}

// round 17
// speedup vs baseline: 1.1023x; 1.0508x over previous
#include <cuda_runtime.h>
#include <cuda_bf16.h>

#define NN 8192
#define T  64
#define NT (NN / T)                 // 128
#define NPAIR (NT * (NT + 1) / 2)   // 8256 tile pairs

// Deterministic partial row sums: g_part[k][i] = degree contribution to row i
// from tile-column k. Written exactly once per slot. 4 MB scratch.
__device__ float g_part[NT * NN];
__device__ float g_dis[NN];

// Decode linear pair index -> (bi, bj), bi <= bj, row-major over upper triangle.
__device__ __forceinline__ void pair_decode(int idx, int& bi, int& bj) {
    const int M2 = 2 * NT + 1;
    int i = (int)(((float)M2 - sqrtf((float)M2 * (float)M2 - 8.0f * (float)idx)) * 0.5f);
    while ((i * (2 * NT - i + 1)) / 2 > idx) --i;
    while (((i + 1) * (2 * NT - i)) / 2 <= idx) ++i;
    bi = i;
    bj = idx - (i * (2 * NT - i + 1)) / 2 + i;
}

// ---------------------------------------------------------------------------
// Pass 1 (degrees + materialize M^T into out[J,I]).
// adj is read-once-and-dead for the WHOLE schedule now -> __ldcs (evict-first)
// so L2 retains the 129 MB intermediate instead of the dead 256 MB stream.
// Intermediate writes keep DEFAULT policy (must stay L2-resident for pass2).
// ---------------------------------------------------------------------------
__global__ __launch_bounds__(256) void pass1_degrees(const float* __restrict__ adj,
                                                     float* __restrict__ out) {
    int bi, bj;
    pair_decode(blockIdx.x, bi, bj);

    __shared__ float Bs[T][T + 1];
    __shared__ float rpartS[4][T];
    __shared__ float cpartS[4][T];

    const int t  = threadIdx.x;
    const int c  = t & 63;
    const int rg = t >> 6;
    const size_t I0 = (size_t)bi * T, J0 = (size_t)bj * T;

    // Prefetch the 16 A values this thread will consume (coalesced, streaming).
    float a[16];
    #pragma unroll
    for (int k = 0; k < 16; ++k)
        a[k] = __ldcs(&adj[(I0 + rg * 16 + k) * NN + J0 + c]);

    // Stage B (coalesced streaming LDG; STS bank (rr + c)%32 -> conflict-free).
    #pragma unroll
    for (int k = 0; k < 16; ++k) {
        int rr = rg * 16 + k;
        Bs[rr][c] = __ldcs(&adj[(J0 + rr) * NN + I0 + c]);
    }
    __syncthreads();

    const bool diag = (bi == bj);
    float colAcc = 0.0f;

    // m = max(A, B^T); column sums in a register; store m back in place.
    #pragma unroll
    for (int k = 0; k < 16; ++k) {
        int r = rg * 16 + k;
        float m = fmaxf(a[k], Bs[c][r]);         // bank (c+r)%32 -> conflict-free
        if (diag && r == c) m = 1.0f;
        colAcc += m;
        Bs[c][r] = m;                            // same slot just read -> no hazard
    }
    cpartS[rg][c] = colAcc;
    __syncthreads();

    // Bs[rr][c] = M^T[rr][c]: stream the M^T tile to out[J,I] (DEFAULT policy,
    // wants to live in L2) while accumulating the row sums of M.
    float rowAcc = 0.0f;
    #pragma unroll
    for (int k = 0; k < 16; ++k) {
        int rr = rg * 16 + k;
        float v = Bs[rr][c];
        rowAcc += v;
        out[(J0 + rr) * NN + I0 + c] = v;        // M^T tile -> out[J,I], coalesced
    }
    rpartS[rg][c] = rowAcc;
    __syncthreads();

    if (t < T) {
        g_part[bj * NN + I0 + t] =
            (rpartS[0][t] + rpartS[1][t]) + (rpartS[2][t] + rpartS[3][t]);
        if (!diag)
            g_part[bi * NN + J0 + t] =
                (cpartS[0][t] + cpartS[1][t]) + (cpartS[2][t] + cpartS[3][t]);
    }
}

// ---------------------------------------------------------------------------
// Degree reduce + rsqrt: 128 blocks; 4 k-slices per row combined via smem.
// Fully coalesced, deterministic fixed-order sums.
// ---------------------------------------------------------------------------
__global__ __launch_bounds__(256) void reduce_rsqrt_kernel() {
    __shared__ float part[4][T];
    const int t = threadIdx.x;
    const int i = blockIdx.x * T + (t & 63);
    const int q = t >> 6;

    float s = 0.f;
    #pragma unroll
    for (int kk = 0; kk < NT / 4; ++kk)
        s += g_part[(q + 4 * kk) * NN + i];
    part[q][t & 63] = s;
    __syncthreads();

    if (t < T) {
        float tot = (part[0][t] + part[1][t]) + (part[2][t] + part[3][t]);
        g_dis[blockIdx.x * T + t] = rsqrtf(tot);
    }
}

// ---------------------------------------------------------------------------
// Pass 2 (scale + mirror): reads the M^T tile from out[J,I] (DEFAULT loads —
// these are the L2 hits we protected), scales, writes the fresh upper block
// out[I,J] with __stcs (no reuse: evict-first so its write-allocates don't
// evict intermediate), then overwrites out[J,I] in place with DEFAULT stores
// (lines already resident; kills the dirty intermediate before writeback).
// Reverse triangle order preserved.
// ---------------------------------------------------------------------------
__global__ __launch_bounds__(256) void pass2_write(float* __restrict__ out) {
    int bi, bj;
    pair_decode(NPAIR - 1 - (int)blockIdx.x, bi, bj);

    __shared__ float Bs[T][T + 1];
    __shared__ float dI[T], dJ[T];

    const int t  = threadIdx.x;
    const int c4 = (t & 15) * 4;
    const int rg = t >> 4;
    const size_t I0 = (size_t)bi * T, J0 = (size_t)bj * T;

    // Load M^T tile from the lower-triangle scratch (coalesced float4).
    #pragma unroll
    for (int k = 0; k < 4; ++k) {
        int rr = rg + 16 * k;
        float4 b = *reinterpret_cast<const float4*>(&out[(J0 + rr) * NN + I0 + c4]);
        Bs[rr][c4 + 0] = b.x; Bs[rr][c4 + 1] = b.y;
        Bs[rr][c4 + 2] = b.z; Bs[rr][c4 + 3] = b.w;
    }
    if (t < T)          dI[t]     = g_dis[I0 + t];
    else if (t < 2 * T) dJ[t - T] = g_dis[J0 + (t - T)];
    __syncthreads();

    const bool diag = (bi == bj);
    const float dj0 = dJ[c4 + 0], dj1 = dJ[c4 + 1];
    const float dj2 = dJ[c4 + 2], dj3 = dJ[c4 + 3];

    // Bs[c][r] = M[r][c]. Scale and write the upper block (streaming store);
    // stage the scaled values transposed in place for the mirror block.
    #pragma unroll
    for (int k = 0; k < 4; ++k) {
        int r = rg + 16 * k;
        const float dir = dI[r];
        float4 o;
        o.x = Bs[c4 + 0][r] * dir * dj0;
        o.y = Bs[c4 + 1][r] * dir * dj1;
        o.z = Bs[c4 + 2][r] * dir * dj2;
        o.w = Bs[c4 + 3][r] * dir * dj3;
        __stcs(reinterpret_cast<float4*>(&out[(I0 + r) * NN + J0 + c4]), o);
        Bs[c4 + 0][r] = o.x; Bs[c4 + 1][r] = o.y;     // same slots just read
        Bs[c4 + 2][r] = o.z; Bs[c4 + 3][r] = o.w;
    }

    if (!diag) {
        __syncthreads();
        #pragma unroll
        for (int k = 0; k < 4; ++k) {
            int rr = rg + 16 * k;
            float4 o;
            o.x = Bs[rr][c4 + 0]; o.y = Bs[rr][c4 + 1];
            o.z = Bs[rr][c4 + 2]; o.w = Bs[rr][c4 + 3];
            *reinterpret_cast<float4*>(&out[(J0 + rr) * NN + I0 + c4]) = o;
        }
    }
}

extern "C" void kernel_launch(void* const* d_in, const int* in_sizes, int n_in,
                              void* d_out, int out_size) {
    const float* adj = (const float*)d_in[0];
    float*       out = (float*)d_out;

    pass1_degrees<<<NPAIR, 256>>>(adj, out);
    reduce_rsqrt_kernel<<<NN / T, 256>>>();
    pass2_write<<<NPAIR, 256>>>(out);
}